// round 15
// baseline (speedup 1.0000x reference)
#include <cuda_runtime.h>
#include <math.h>

#define TT  256
#define HH  16
#define DD  128
#define KD  2048
#define HIDN 2048
#define NCG 30
#define RG  8   // build CTAs per head (each owns 16 rows of state)

typedef unsigned long long ull;

// ---- packed f32x2 helpers, "r"-constraint form (validated R7) --------------
__device__ __forceinline__ ull pk2(float lo, float hi) {
    ull r;
    asm("mov.b64 %0, {%1, %2};"
        : "=l"(r) : "r"(__float_as_uint(lo)), "r"(__float_as_uint(hi)));
    return r;
}
__device__ __forceinline__ void upk2(ull v, float& lo, float& hi) {
    unsigned a, b;
    asm("mov.b64 {%0, %1}, %2;" : "=r"(a), "=r"(b) : "l"(v));
    lo = __uint_as_float(a);
    hi = __uint_as_float(b);
}
#define FMA2(d, a, b) asm("fma.rn.f32x2 %0, %1, %2, %0;" : "+l"(d) : "l"(a), "l"(b))

// ---------------- scratch (device globals; no allocations allowed) ----------
__device__ float g_qpre[TT * KD];
__device__ float g_kpre[TT * KD];
__device__ float g_v[TT * KD];
__device__ float g_qn[TT * KD];
__device__ float g_kn[TT * KD];
__device__ float g_on[TT * KD];
__device__ float g_gpart[4][TT * 32];

// Materialized per-timestep states, 256 MB each (fp32).
// float4 idx = ((t*HH + h)*32 + m4)*128 + r ; columns c = 4*m4 .. 4*m4+3.
__device__ float4 g_Hkk4[TT * HH * 32 * 128];
__device__ float4 g_Hkv4[TT * HH * 32 * 128];

// ---------------- 64x64 fp32 GEMM tile, double buffered, f32x2 core ---------
__device__ __forceinline__ void gemm64_tile(const float* __restrict__ A,
                                            const float* __restrict__ B,
                                            float* __restrict__ C,
                                            int N, int K, int row0, int col0)
{
    __shared__ float As[2][16][72];
    __shared__ float Bs[2][16][72];

    int tid = threadIdx.x;
    int tx = tid & 15;
    int ty = tid >> 4;

    int aRow = tid >> 2;
    int aCol = (tid & 3) * 4;
    int bRow = tid >> 4;
    int bCol = (tid & 15) * 4;

    ull acc[8];
#pragma unroll
    for (int i = 0; i < 8; i++) acc[i] = 0ull;

    const float* Ap = A + (size_t)(row0 + aRow) * K + aCol;
    const float* Bp = B + (size_t)bRow * N + col0 + bCol;

    float4 av = *(const float4*)(Ap);
    float4 bv = *(const float4*)(Bp);

    int buf = 0;
    for (int k0 = 0; k0 < K; k0 += 16) {
        As[buf][aCol + 0][aRow] = av.x;
        As[buf][aCol + 1][aRow] = av.y;
        As[buf][aCol + 2][aRow] = av.z;
        As[buf][aCol + 3][aRow] = av.w;
        *(float4*)(&Bs[buf][bRow][bCol]) = bv;
        __syncthreads();

        if (k0 + 16 < K) {
            av = *(const float4*)(Ap + k0 + 16);
            bv = *(const float4*)(Bp + (size_t)(k0 + 16) * N);
        }

#pragma unroll
        for (int kk = 0; kk < 16; kk++) {
            float4 a4 = *(const float4*)(&As[buf][kk][ty * 4]);
            ulonglong2 b2 = *(const ulonglong2*)(&Bs[buf][kk][tx * 4]);
            ull a0 = pk2(a4.x, a4.x);
            ull a1 = pk2(a4.y, a4.y);
            ull a2 = pk2(a4.z, a4.z);
            ull a3 = pk2(a4.w, a4.w);
            FMA2(acc[0], a0, b2.x); FMA2(acc[1], a0, b2.y);
            FMA2(acc[2], a1, b2.x); FMA2(acc[3], a1, b2.y);
            FMA2(acc[4], a2, b2.x); FMA2(acc[5], a2, b2.y);
            FMA2(acc[6], a3, b2.x); FMA2(acc[7], a3, b2.y);
        }
        buf ^= 1;
    }

#pragma unroll
    for (int i = 0; i < 4; i++) {
        float4 res;
        upk2(acc[2 * i + 0], res.x, res.y);
        upk2(acc[2 * i + 1], res.z, res.w);
        *(float4*)(C + (size_t)(row0 + ty * 4 + i) * N + col0 + tx * 4) = res;
    }
}

// fused QKV: grid (96, 4) -> sel = bx>>5 chooses Wq/Wk/Wv and target buffer
__global__ __launch_bounds__(256) void sgemm_qkv(const float* __restrict__ x,
                                                 const float* __restrict__ Wq,
                                                 const float* __restrict__ Wk,
                                                 const float* __restrict__ Wv,
                                                 float* __restrict__ qpre,
                                                 float* __restrict__ kpre,
                                                 float* __restrict__ vbuf)
{
    int sel = blockIdx.x >> 5;
    int bxl = blockIdx.x & 31;
    const float* B = (sel == 0) ? Wq : (sel == 1) ? Wk : Wv;
    float* C = (sel == 0) ? qpre : (sel == 1) ? kpre : vbuf;
    gemm64_tile(x, B, C, KD, HIDN, blockIdx.y * 64, bxl * 64);
}

__global__ __launch_bounds__(256) void sgemm_o(const float* __restrict__ A,
                                               const float* __restrict__ B,
                                               float* __restrict__ C)
{
    gemm64_tile(A, B, C, HIDN, KD, blockIdx.y * 64, blockIdx.x * 64);
}

// ---------------- prep: fused conv+l2norm (bx<8192) & gates partial (rest) --
__global__ __launch_bounds__(128) void prep_kernel(const float* __restrict__ x,
                                                   const float* __restrict__ Wa,
                                                   const float* __restrict__ Wb,
                                                   const float* __restrict__ pre_q,
                                                   const float* __restrict__ cw_q,
                                                   float* __restrict__ out_q,
                                                   const float* __restrict__ pre_k,
                                                   const float* __restrict__ cw_k,
                                                   float* __restrict__ out_k)
{
    __shared__ float smem_pool[4 * 128 + 128 * 32];
    int tid = threadIdx.x;

    if (blockIdx.x < 8192) {
        int bx = blockIdx.x;
        int t = bx & 255;
        int h = (bx >> 8) & 15;
        int z = bx >> 12;
        const float* pre = z ? pre_k : pre_q;
        const float* cw  = z ? cw_k  : cw_q;
        float* outp      = z ? out_k : out_q;

        int d = tid;
        int c = h * DD + d;

        float w0 = cw[c * 4 + 0], w1 = cw[c * 4 + 1];
        float w2 = cw[c * 4 + 2], w3 = cw[c * 4 + 3];

        float y = pre[(size_t)t * KD + c] * w3;
        if (t >= 1) y += pre[(size_t)(t - 1) * KD + c] * w2;
        if (t >= 2) y += pre[(size_t)(t - 2) * KD + c] * w1;
        if (t >= 3) y += pre[(size_t)(t - 3) * KD + c] * w0;
        y = y / (1.f + expf(-y));  // silu

        float s = y * y;
#pragma unroll
        for (int o = 16; o; o >>= 1) s += __shfl_xor_sync(0xffffffffu, s, o);
        if ((tid & 31) == 0) smem_pool[tid >> 5] = s;
        __syncthreads();
        float tot = smem_pool[0] + smem_pool[1] + smem_pool[2] + smem_pool[3];
        outp[(size_t)t * KD + c] = y * rsqrtf(tot + 1e-6f);
    } else {
        int idx = blockIdx.x - 8192;  // 0..255
        int ks = idx & 3;
        int t0 = (idx >> 2) * 4;
        int row = tid >> 5;
        int col = tid & 31;

        float* sx = smem_pool;        // [4][128]
        float* sw = smem_pool + 512;  // [128][32]

        float acc = 0.f;
        for (int k0 = ks * 512; k0 < ks * 512 + 512; k0 += 128) {
            {
                int r = tid >> 5, c4 = tid & 31;
                float4 v = *(const float4*)(x + (size_t)(t0 + r) * HIDN + k0 + c4 * 4);
                *(float4*)(sx + r * 128 + c4 * 4) = v;
            }
#pragma unroll
            for (int s = 0; s < 32; s++) {
                int id2 = tid + 128 * s;
                int r = id2 >> 5, c = id2 & 31;
                sw[r * 32 + c] = (c < 16) ? Wa[(size_t)(k0 + r) * HH + c]
                                          : Wb[(size_t)(k0 + r) * HH + (c - 16)];
            }
            __syncthreads();

#pragma unroll
            for (int i4 = 0; i4 < 32; i4++) {
                float4 xv = *(const float4*)(sx + row * 128 + i4 * 4);
                acc += xv.x * sw[(i4 * 4 + 0) * 32 + col];
                acc += xv.y * sw[(i4 * 4 + 1) * 32 + col];
                acc += xv.z * sw[(i4 * 4 + 2) * 32 + col];
                acc += xv.w * sw[(i4 * 4 + 3) * 32 + col];
            }
            __syncthreads();
        }
        g_gpart[ks][(t0 + row) * 32 + col] = acc;
    }
}

// ---------------- phase 1: build & materialize H states ---------------------
__global__ __launch_bounds__(256) void build_kernel(const float* __restrict__ ba,
                                                    const float* __restrict__ bb)
{
    int rg = blockIdx.x;
    int h  = blockIdx.y;
    int tid = threadIdx.x;
    int r_loc = tid & 15;
    int cc = tid >> 4;
    int r = rg * 16 + r_loc;
    int c4 = cc >> 2;
    int j0 = (cc & 3) * 2;

    __shared__ float4 sk4[2][32], sv4[2][32];
    __shared__ float sdecay[TT], sbeta[TT];

    {
        int t = tid;
        float ds = g_gpart[0][t * 32 + h] + g_gpart[1][t * 32 + h]
                 + g_gpart[2][t * 32 + h] + g_gpart[3][t * 32 + h];
        sdecay[t] = 1.f / (1.f + expf(-(ds + ba[h])));
        float bs = g_gpart[0][t * 32 + 16 + h] + g_gpart[1][t * 32 + 16 + h]
                 + g_gpart[2][t * 32 + 16 + h] + g_gpart[3][t * 32 + 16 + h];
        sbeta[t] = 1.f / (1.f + expf(-(bs + bb[h])));
    }

    float Akk[8], Mkv[8];
#pragma unroll
    for (int i = 0; i < 8; i++) { Akk[i] = 0.f; Mkv[i] = 0.f; }

    const float4* kn4 = (const float4*)g_kn;
    const float4* v4g = (const float4*)g_v;

    float4 pf = make_float4(0.f, 0.f, 0.f, 0.f);
    {
        int b = h * 32;
        if (tid < 32) pf = kn4[b + tid];
        else if (tid < 64) pf = v4g[b + tid - 32];
    }

    for (int t = 0; t < TT; t++) {
        int buf = t & 1;
        if (tid < 32) sk4[buf][tid] = pf;
        else if (tid < 64) sv4[buf][tid - 32] = pf;

        if (t + 1 < TT) {
            int b = ((t + 1) * HH + h) * 32;
            if (tid < 32) pf = kn4[b + tid];
            else if (tid < 64) pf = v4g[b + tid - 32];
        }
        __syncthreads();

        float decay = sdecay[t], bet = sbeta[t];
        const float* skf = (const float*)sk4[buf];
        const float* svf = (const float*)sv4[buf];
        float bkr = bet * skf[r];
        float bvr = bet * svf[r];
        float4 kc0 = sk4[buf][cc * 2];
        float4 kc1 = sk4[buf][cc * 2 + 1];

        Akk[0] = Akk[0] * decay + bkr * kc0.x;
        Akk[1] = Akk[1] * decay + bkr * kc0.y;
        Akk[2] = Akk[2] * decay + bkr * kc0.z;
        Akk[3] = Akk[3] * decay + bkr * kc0.w;
        Akk[4] = Akk[4] * decay + bkr * kc1.x;
        Akk[5] = Akk[5] * decay + bkr * kc1.y;
        Akk[6] = Akk[6] * decay + bkr * kc1.z;
        Akk[7] = Akk[7] * decay + bkr * kc1.w;

        Mkv[0] = Mkv[0] * decay + bvr * kc0.x;
        Mkv[1] = Mkv[1] * decay + bvr * kc0.y;
        Mkv[2] = Mkv[2] * decay + bvr * kc0.z;
        Mkv[3] = Mkv[3] * decay + bvr * kc0.w;
        Mkv[4] = Mkv[4] * decay + bvr * kc1.x;
        Mkv[5] = Mkv[5] * decay + bvr * kc1.y;
        Mkv[6] = Mkv[6] * decay + bvr * kc1.z;
        Mkv[7] = Mkv[7] * decay + bvr * kc1.w;

        size_t base = ((size_t)(t * HH + h) * 4 + c4) * 8;
        g_Hkk4[(base + j0 + 0) * 128 + r] = make_float4(Akk[0], Akk[1], Akk[2], Akk[3]);
        g_Hkk4[(base + j0 + 1) * 128 + r] = make_float4(Akk[4], Akk[5], Akk[6], Akk[7]);
        g_Hkv4[(base + j0 + 0) * 128 + r] = make_float4(Mkv[0], Mkv[1], Mkv[2], Mkv[3]);
        g_Hkv4[(base + j0 + 1) * 128 + r] = make_float4(Mkv[4], Mkv[5], Mkv[6], Mkv[7]);
    }
}

// ---------------- phase 2: parallel CG solve per (t, h) ---------------------
// 256 threads; row r = tid>>1 split across a lane-adjacent thread PAIR
// (half = tid&1, 64 scalar A-regs each). Pair combine = one shfl_xor(1) —
// no extra barrier. Residual-carried CG (R11-proven): 2 exact dot-product
// reductions, 2 barriers/iter. Profile-driven (R13): solve is warp-starved
// (occ 12.4%, issue 23.8%) -> halve regs/thread, double warps, halve chains.
__global__ __launch_bounds__(256, 2) void solve_kernel(const float* __restrict__ lam,
                                                       const float* __restrict__ onw)
{
    int t = blockIdx.x;
    int h = blockIdx.y;
    int tid = threadIdx.x;
    int r = tid >> 1;        // row 0..127
    int half = tid & 1;      // column half: cols [64*half, 64*half+64)
    int warp = tid >> 5;
    int lane = tid & 31;

    __shared__ float sr[DD];          // residual vector broadcast
    __shared__ float redA[8], redB[8];

    size_t mbase = (size_t)(t * HH + h) * 32 + 16 * half;

    // half A row in registers: Areg[lc] = A[r][64*half + lc]
    float Areg[64];
#pragma unroll
    for (int m = 0; m < 16; m++) {
        float4 a = g_Hkk4[(mbase + m) * 128 + r];
        Areg[4 * m + 0] = a.x;
        Areg[4 * m + 1] = a.y;
        Areg[4 * m + 2] = a.z;
        Areg[4 * m + 3] = a.w;
    }
    if ((r >> 6) == half) {
        float lp = lam[h * DD + r];
        Areg[r & 63] += log1pf(expf(lp)) + 0.25f;
    }

    // CG init: x = 0, r0 = b = q, p0 = r0, Ap_old = 0, beta_0 = 0
    float b = g_qn[(t * HH + h) * DD + r];
    float rr = b, xr = 0.f;
    float pold = 0.f, Apold = 0.f, bcg = 0.f;
    if (half == 0) sr[r] = b;
    {
        float s = b * b;   // each row contributes twice; halved below
#pragma unroll
        for (int o = 16; o; o >>= 1) s += __shfl_xor_sync(0xffffffffu, s, o);
        if (lane == 0) redB[warp] = s;
    }
    __syncthreads();
    float rs = 0.5f * (((redB[0] + redB[1]) + (redB[2] + redB[3]))
                     + ((redB[4] + redB[5]) + (redB[6] + redB[7])));
    float rs_tol = rs * 1e-14f;

    const float4* sr4 = (const float4*)sr;
    for (int it = 0; it < NCG; it++) {
        // partial Ar over this thread's 64 columns, then pair-combine
        float a0 = 0.f, a1 = 0.f, a2 = 0.f, a3 = 0.f;
#pragma unroll
        for (int m = 0; m < 16; m++) {
            float4 rv = sr4[16 * half + m];
            a0 += Areg[4 * m + 0] * rv.x;
            a1 += Areg[4 * m + 1] * rv.y;
            a2 += Areg[4 * m + 2] * rv.z;
            a3 += Areg[4 * m + 3] * rv.w;
        }
        float part = (a0 + a1) + (a2 + a3);
        float Ar = part + __shfl_xor_sync(0xffffffffu, part, 1);

        // p_i = r_i + beta*p_{i-1};  Ap_i = A r_i + beta*Ap_{i-1}
        float p  = rr + bcg * pold;
        float Ap = Ar + bcg * Apold;

        // exact reduction: p . Ap (pair-duplicated; halved at the end)
        float c = p * Ap;
#pragma unroll
        for (int o = 16; o; o >>= 1) c += __shfl_xor_sync(0xffffffffu, c, o);
        if (lane == 0) redA[warp] = c;
        __syncthreads();

        float pAp = 0.5f * (((redA[0] + redA[1]) + (redA[2] + redA[3]))
                          + ((redA[4] + redA[5]) + (redA[6] + redA[7])));
        float alpha = rs / (pAp + 1e-12f);
        xr += alpha * p;
        rr -= alpha * Ap;
        if (half == 0) sr[r] = rr;    // residual for next matvec

        // exact reduction: r_new . r_new (pair-duplicated; halved)
        float s = rr * rr;
#pragma unroll
        for (int o = 16; o; o >>= 1) s += __shfl_xor_sync(0xffffffffu, s, o);
        if (lane == 0) redB[warp] = s;
        __syncthreads();

        float rsn = 0.5f * (((redB[0] + redB[1]) + (redB[2] + redB[3]))
                          + ((redB[4] + redB[5]) + (redB[6] + redB[7])));
        bcg = rsn / (rs + 1e-12f);
        rs = rsn;
        pold = p;
        Apold = Ap;

        if (rsn < rs_tol) break;  // converged to fp32 floor; rest are no-ops
    }

    // broadcast x via sr; reuse Areg for Hkv^T half-row
    if (half == 0) sr[r] = xr;
#pragma unroll
    for (int m = 0; m < 16; m++) {
        float4 a = g_Hkv4[(mbase + m) * 128 + r];
        Areg[4 * m + 0] = a.x;
        Areg[4 * m + 1] = a.y;
        Areg[4 * m + 2] = a.z;
        Areg[4 * m + 3] = a.w;
    }
    __syncthreads();

    float a0 = 0.f, a1 = 0.f, a2 = 0.f, a3 = 0.f;
#pragma unroll
    for (int m = 0; m < 16; m++) {
        float4 xv = sr4[16 * half + m];
        a0 += Areg[4 * m + 0] * xv.x;
        a1 += Areg[4 * m + 1] * xv.y;
        a2 += Areg[4 * m + 2] * xv.z;
        a3 += Areg[4 * m + 3] * xv.w;
    }
    float part = (a0 + a1) + (a2 + a3);
    float o = part + __shfl_xor_sync(0xffffffffu, part, 1);

    float s2 = o * o;   // pair-duplicated; halved below
#pragma unroll
    for (int o2 = 16; o2; o2 >>= 1) s2 += __shfl_xor_sync(0xffffffffu, s2, o2);
    if (lane == 0) redB[warp] = s2;
    __syncthreads();

    float ms = 0.5f * (((redB[0] + redB[1]) + (redB[2] + redB[3]))
                     + ((redB[4] + redB[5]) + (redB[6] + redB[7]))) * (1.0f / 128.0f);
    if (half == 0)
        g_on[(t * HH + h) * DD + r] = o * rsqrtf(ms + 1e-5f) * onw[r];
}

// ---------------- launch ----------------------------------------------------
extern "C" void kernel_launch(void* const* d_in, const int* in_sizes, int n_in,
                              void* d_out, int out_size)
{
    const float* x   = (const float*)d_in[0];
    const float* Wq  = (const float*)d_in[1];
    const float* Wk  = (const float*)d_in[2];
    const float* Wv  = (const float*)d_in[3];
    const float* Wa  = (const float*)d_in[4];
    const float* ba  = (const float*)d_in[5];
    const float* Wb  = (const float*)d_in[6];
    const float* bb  = (const float*)d_in[7];
    const float* cwq = (const float*)d_in[8];
    const float* cwk = (const float*)d_in[9];
    const float* lam = (const float*)d_in[10];
    const float* onw = (const float*)d_in[11];
    const float* Wo  = (const float*)d_in[12];
    float* out = (float*)d_out;

    float *qpre, *kpre, *vbuf, *qn, *kn, *onorm;
    cudaGetSymbolAddress((void**)&qpre,  g_qpre);
    cudaGetSymbolAddress((void**)&kpre,  g_kpre);
    cudaGetSymbolAddress((void**)&vbuf,  g_v);
    cudaGetSymbolAddress((void**)&qn,    g_qn);
    cudaGetSymbolAddress((void**)&kn,    g_kn);
    cudaGetSymbolAddress((void**)&onorm, g_on);

    sgemm_qkv<<<dim3(96, 4), 256>>>(x, Wq, Wk, Wv, qpre, kpre, vbuf);          // 0
    prep_kernel<<<8192 + 256, 128>>>(x, Wa, Wb, qpre, cwq, qn, kpre, cwk, kn); // 1
    build_kernel<<<dim3(RG, HH), 256>>>(ba, bb);                               // 2
    solve_kernel<<<dim3(TT, HH), 256>>>(lam, onw);                             // 3 <- ncu
    sgemm_o<<<dim3(HIDN / 64, TT / 64), 256>>>(onorm, Wo, out);                // 4
}

// round 16
// speedup vs baseline: 1.2406x; 1.2406x over previous
#include <cuda_runtime.h>
#include <math.h>

#define TT  256
#define HH  16
#define DD  128
#define KD  2048
#define HIDN 2048
#define NCG 30
#define RG  8   // build CTAs per head (each owns 16 rows of state)

typedef unsigned long long ull;

// ---- packed f32x2 helpers, "r"-constraint form (validated R7) --------------
__device__ __forceinline__ ull pk2(float lo, float hi) {
    ull r;
    asm("mov.b64 %0, {%1, %2};"
        : "=l"(r) : "r"(__float_as_uint(lo)), "r"(__float_as_uint(hi)));
    return r;
}
__device__ __forceinline__ void upk2(ull v, float& lo, float& hi) {
    unsigned a, b;
    asm("mov.b64 {%0, %1}, %2;" : "=r"(a), "=r"(b) : "l"(v));
    lo = __uint_as_float(a);
    hi = __uint_as_float(b);
}
#define FMA2(d, a, b) asm("fma.rn.f32x2 %0, %1, %2, %0;" : "+l"(d) : "l"(a), "l"(b))

// ---------------- scratch (device globals; no allocations allowed) ----------
__device__ float g_qpre[TT * KD];
__device__ float g_kpre[TT * KD];
__device__ float g_v[TT * KD];
__device__ float g_qn[TT * KD];
__device__ float g_kn[TT * KD];
__device__ float g_on[TT * KD];
__device__ float g_gpart[4][TT * 32];

// Materialized per-timestep states, 256 MB each (fp32).
// float4 idx = ((t*HH + h)*32 + m4)*128 + r ; columns c = 4*m4 .. 4*m4+3.
__device__ float4 g_Hkk4[TT * HH * 32 * 128];
__device__ float4 g_Hkv4[TT * HH * 32 * 128];

// ---------------- 64x64 fp32 GEMM tile, double buffered, f32x2 core ---------
__device__ __forceinline__ void gemm64_tile(const float* __restrict__ A,
                                            const float* __restrict__ B,
                                            float* __restrict__ C,
                                            int N, int K, int row0, int col0)
{
    __shared__ float As[2][16][72];
    __shared__ float Bs[2][16][72];

    int tid = threadIdx.x;
    int tx = tid & 15;
    int ty = tid >> 4;

    int aRow = tid >> 2;
    int aCol = (tid & 3) * 4;
    int bRow = tid >> 4;
    int bCol = (tid & 15) * 4;

    ull acc[8];
#pragma unroll
    for (int i = 0; i < 8; i++) acc[i] = 0ull;

    const float* Ap = A + (size_t)(row0 + aRow) * K + aCol;
    const float* Bp = B + (size_t)bRow * N + col0 + bCol;

    float4 av = *(const float4*)(Ap);
    float4 bv = *(const float4*)(Bp);

    int buf = 0;
    for (int k0 = 0; k0 < K; k0 += 16) {
        As[buf][aCol + 0][aRow] = av.x;
        As[buf][aCol + 1][aRow] = av.y;
        As[buf][aCol + 2][aRow] = av.z;
        As[buf][aCol + 3][aRow] = av.w;
        *(float4*)(&Bs[buf][bRow][bCol]) = bv;
        __syncthreads();

        if (k0 + 16 < K) {
            av = *(const float4*)(Ap + k0 + 16);
            bv = *(const float4*)(Bp + (size_t)(k0 + 16) * N);
        }

#pragma unroll
        for (int kk = 0; kk < 16; kk++) {
            float4 a4 = *(const float4*)(&As[buf][kk][ty * 4]);
            ulonglong2 b2 = *(const ulonglong2*)(&Bs[buf][kk][tx * 4]);
            ull a0 = pk2(a4.x, a4.x);
            ull a1 = pk2(a4.y, a4.y);
            ull a2 = pk2(a4.z, a4.z);
            ull a3 = pk2(a4.w, a4.w);
            FMA2(acc[0], a0, b2.x); FMA2(acc[1], a0, b2.y);
            FMA2(acc[2], a1, b2.x); FMA2(acc[3], a1, b2.y);
            FMA2(acc[4], a2, b2.x); FMA2(acc[5], a2, b2.y);
            FMA2(acc[6], a3, b2.x); FMA2(acc[7], a3, b2.y);
        }
        buf ^= 1;
    }

#pragma unroll
    for (int i = 0; i < 4; i++) {
        float4 res;
        upk2(acc[2 * i + 0], res.x, res.y);
        upk2(acc[2 * i + 1], res.z, res.w);
        *(float4*)(C + (size_t)(row0 + ty * 4 + i) * N + col0 + tx * 4) = res;
    }
}

// fused QKV: grid (96, 4) -> sel = bx>>5 chooses Wq/Wk/Wv and target buffer
__global__ __launch_bounds__(256) void sgemm_qkv(const float* __restrict__ x,
                                                 const float* __restrict__ Wq,
                                                 const float* __restrict__ Wk,
                                                 const float* __restrict__ Wv,
                                                 float* __restrict__ qpre,
                                                 float* __restrict__ kpre,
                                                 float* __restrict__ vbuf)
{
    int sel = blockIdx.x >> 5;
    int bxl = blockIdx.x & 31;
    const float* B = (sel == 0) ? Wq : (sel == 1) ? Wk : Wv;
    float* C = (sel == 0) ? qpre : (sel == 1) ? kpre : vbuf;
    gemm64_tile(x, B, C, KD, HIDN, blockIdx.y * 64, bxl * 64);
}

__global__ __launch_bounds__(256) void sgemm_o(const float* __restrict__ A,
                                               const float* __restrict__ B,
                                               float* __restrict__ C)
{
    gemm64_tile(A, B, C, HIDN, KD, blockIdx.y * 64, blockIdx.x * 64);
}

// ---------------- prep: fused conv+l2norm (bx<8192) & gates partial (rest) --
__global__ __launch_bounds__(128) void prep_kernel(const float* __restrict__ x,
                                                   const float* __restrict__ Wa,
                                                   const float* __restrict__ Wb,
                                                   const float* __restrict__ pre_q,
                                                   const float* __restrict__ cw_q,
                                                   float* __restrict__ out_q,
                                                   const float* __restrict__ pre_k,
                                                   const float* __restrict__ cw_k,
                                                   float* __restrict__ out_k)
{
    __shared__ float smem_pool[4 * 128 + 128 * 32];
    int tid = threadIdx.x;

    if (blockIdx.x < 8192) {
        int bx = blockIdx.x;
        int t = bx & 255;
        int h = (bx >> 8) & 15;
        int z = bx >> 12;
        const float* pre = z ? pre_k : pre_q;
        const float* cw  = z ? cw_k  : cw_q;
        float* outp      = z ? out_k : out_q;

        int d = tid;
        int c = h * DD + d;

        float w0 = cw[c * 4 + 0], w1 = cw[c * 4 + 1];
        float w2 = cw[c * 4 + 2], w3 = cw[c * 4 + 3];

        float y = pre[(size_t)t * KD + c] * w3;
        if (t >= 1) y += pre[(size_t)(t - 1) * KD + c] * w2;
        if (t >= 2) y += pre[(size_t)(t - 2) * KD + c] * w1;
        if (t >= 3) y += pre[(size_t)(t - 3) * KD + c] * w0;
        y = y / (1.f + expf(-y));  // silu

        float s = y * y;
#pragma unroll
        for (int o = 16; o; o >>= 1) s += __shfl_xor_sync(0xffffffffu, s, o);
        if ((tid & 31) == 0) smem_pool[tid >> 5] = s;
        __syncthreads();
        float tot = smem_pool[0] + smem_pool[1] + smem_pool[2] + smem_pool[3];
        outp[(size_t)t * KD + c] = y * rsqrtf(tot + 1e-6f);
    } else {
        int idx = blockIdx.x - 8192;  // 0..255
        int ks = idx & 3;
        int t0 = (idx >> 2) * 4;
        int row = tid >> 5;
        int col = tid & 31;

        float* sx = smem_pool;        // [4][128]
        float* sw = smem_pool + 512;  // [128][32]

        float acc = 0.f;
        for (int k0 = ks * 512; k0 < ks * 512 + 512; k0 += 128) {
            {
                int r = tid >> 5, c4 = tid & 31;
                float4 v = *(const float4*)(x + (size_t)(t0 + r) * HIDN + k0 + c4 * 4);
                *(float4*)(sx + r * 128 + c4 * 4) = v;
            }
#pragma unroll
            for (int s = 0; s < 32; s++) {
                int id2 = tid + 128 * s;
                int r = id2 >> 5, c = id2 & 31;
                sw[r * 32 + c] = (c < 16) ? Wa[(size_t)(k0 + r) * HH + c]
                                          : Wb[(size_t)(k0 + r) * HH + (c - 16)];
            }
            __syncthreads();

#pragma unroll
            for (int i4 = 0; i4 < 32; i4++) {
                float4 xv = *(const float4*)(sx + row * 128 + i4 * 4);
                acc += xv.x * sw[(i4 * 4 + 0) * 32 + col];
                acc += xv.y * sw[(i4 * 4 + 1) * 32 + col];
                acc += xv.z * sw[(i4 * 4 + 2) * 32 + col];
                acc += xv.w * sw[(i4 * 4 + 3) * 32 + col];
            }
            __syncthreads();
        }
        g_gpart[ks][(t0 + row) * 32 + col] = acc;
    }
}

// ---------------- phase 1: build & materialize H states ---------------------
__global__ __launch_bounds__(256) void build_kernel(const float* __restrict__ ba,
                                                    const float* __restrict__ bb)
{
    int rg = blockIdx.x;
    int h  = blockIdx.y;
    int tid = threadIdx.x;
    int r_loc = tid & 15;
    int cc = tid >> 4;
    int r = rg * 16 + r_loc;
    int c4 = cc >> 2;
    int j0 = (cc & 3) * 2;

    __shared__ float4 sk4[2][32], sv4[2][32];
    __shared__ float sdecay[TT], sbeta[TT];

    {
        int t = tid;
        float ds = g_gpart[0][t * 32 + h] + g_gpart[1][t * 32 + h]
                 + g_gpart[2][t * 32 + h] + g_gpart[3][t * 32 + h];
        sdecay[t] = 1.f / (1.f + expf(-(ds + ba[h])));
        float bs = g_gpart[0][t * 32 + 16 + h] + g_gpart[1][t * 32 + 16 + h]
                 + g_gpart[2][t * 32 + 16 + h] + g_gpart[3][t * 32 + 16 + h];
        sbeta[t] = 1.f / (1.f + expf(-(bs + bb[h])));
    }

    float Akk[8], Mkv[8];
#pragma unroll
    for (int i = 0; i < 8; i++) { Akk[i] = 0.f; Mkv[i] = 0.f; }

    const float4* kn4 = (const float4*)g_kn;
    const float4* v4g = (const float4*)g_v;

    float4 pf = make_float4(0.f, 0.f, 0.f, 0.f);
    {
        int b = h * 32;
        if (tid < 32) pf = kn4[b + tid];
        else if (tid < 64) pf = v4g[b + tid - 32];
    }

    for (int t = 0; t < TT; t++) {
        int buf = t & 1;
        if (tid < 32) sk4[buf][tid] = pf;
        else if (tid < 64) sv4[buf][tid - 32] = pf;

        if (t + 1 < TT) {
            int b = ((t + 1) * HH + h) * 32;
            if (tid < 32) pf = kn4[b + tid];
            else if (tid < 64) pf = v4g[b + tid - 32];
        }
        __syncthreads();

        float decay = sdecay[t], bet = sbeta[t];
        const float* skf = (const float*)sk4[buf];
        const float* svf = (const float*)sv4[buf];
        float bkr = bet * skf[r];
        float bvr = bet * svf[r];
        float4 kc0 = sk4[buf][cc * 2];
        float4 kc1 = sk4[buf][cc * 2 + 1];

        Akk[0] = Akk[0] * decay + bkr * kc0.x;
        Akk[1] = Akk[1] * decay + bkr * kc0.y;
        Akk[2] = Akk[2] * decay + bkr * kc0.z;
        Akk[3] = Akk[3] * decay + bkr * kc0.w;
        Akk[4] = Akk[4] * decay + bkr * kc1.x;
        Akk[5] = Akk[5] * decay + bkr * kc1.y;
        Akk[6] = Akk[6] * decay + bkr * kc1.z;
        Akk[7] = Akk[7] * decay + bkr * kc1.w;

        Mkv[0] = Mkv[0] * decay + bvr * kc0.x;
        Mkv[1] = Mkv[1] * decay + bvr * kc0.y;
        Mkv[2] = Mkv[2] * decay + bvr * kc0.z;
        Mkv[3] = Mkv[3] * decay + bvr * kc0.w;
        Mkv[4] = Mkv[4] * decay + bvr * kc1.x;
        Mkv[5] = Mkv[5] * decay + bvr * kc1.y;
        Mkv[6] = Mkv[6] * decay + bvr * kc1.z;
        Mkv[7] = Mkv[7] * decay + bvr * kc1.w;

        size_t base = ((size_t)(t * HH + h) * 4 + c4) * 8;
        g_Hkk4[(base + j0 + 0) * 128 + r] = make_float4(Akk[0], Akk[1], Akk[2], Akk[3]);
        g_Hkk4[(base + j0 + 1) * 128 + r] = make_float4(Akk[4], Akk[5], Akk[6], Akk[7]);
        g_Hkv4[(base + j0 + 0) * 128 + r] = make_float4(Mkv[0], Mkv[1], Mkv[2], Mkv[3]);
        g_Hkv4[(base + j0 + 1) * 128 + r] = make_float4(Mkv[4], Mkv[5], Mkv[6], Mkv[7]);
    }
}

// ---------------- phase 2: parallel CG solve per (t, h) ---------------------
// R11-proven structure: 128 threads; thread r owns FULL row r of A in scalar
// registers; residual-carried CG with 2 exact dot-product reductions and
// 2 barriers/iter. This round's chain-only tweaks:
//   - 8 matvec accumulators (FFMA chain 128 -> 64 cyc)
//   - __fdividef for alpha/beta (saves ~80 cyc/iter of division latency)
// Lesson bank: in-warp column splits double LDS phases (R15); f32x2 here
// loses to latency (R9/R13); analytic residual NaNs (R6/R10).
__global__ __launch_bounds__(128, 3) void solve_kernel(const float* __restrict__ lam,
                                                       const float* __restrict__ onw)
{
    int t = blockIdx.x;
    int h = blockIdx.y;
    int tid = threadIdx.x;
    int r = tid;
    int warp = tid >> 5;
    int lane = tid & 31;

    __shared__ float sr[DD];          // residual vector broadcast
    __shared__ float redA[4], redB[4];

    size_t mbase = (size_t)(t * HH + h) * 32;

    // full A row in registers (Areg[c] = A[r][c])
    float Areg[DD];
#pragma unroll
    for (int m4 = 0; m4 < 32; m4++) {
        float4 a = g_Hkk4[(mbase + m4) * 128 + r];
        Areg[4 * m4 + 0] = a.x;
        Areg[4 * m4 + 1] = a.y;
        Areg[4 * m4 + 2] = a.z;
        Areg[4 * m4 + 3] = a.w;
    }
    {
        float lp = lam[h * DD + r];
        Areg[r] += log1pf(expf(lp)) + 0.25f;
    }

    // CG init: x = 0, r0 = b = q, p0 = r0, Ap_old = 0, beta_0 = 0
    float b = g_qn[(t * HH + h) * DD + r];
    float rr = b, xr = 0.f;
    float pold = 0.f, Apold = 0.f, bcg = 0.f;
    sr[r] = b;
    {
        float s = b * b;
#pragma unroll
        for (int o = 16; o; o >>= 1) s += __shfl_xor_sync(0xffffffffu, s, o);
        if (lane == 0) redB[warp] = s;
    }
    __syncthreads();
    float rs = redB[0] + redB[1] + redB[2] + redB[3];
    float rs_tol = rs * 1e-14f;

    const float4* sr4 = (const float4*)sr;
    for (int it = 0; it < NCG; it++) {
        // Ar[r] = A row . r  — 8 accumulators, 16-deep chains
        float a0 = 0.f, a1 = 0.f, a2 = 0.f, a3 = 0.f;
        float a4 = 0.f, a5 = 0.f, a6 = 0.f, a7 = 0.f;
#pragma unroll
        for (int m4 = 0; m4 < 16; m4++) {
            float4 rv0 = sr4[2 * m4 + 0];
            float4 rv1 = sr4[2 * m4 + 1];
            a0 += Areg[8 * m4 + 0] * rv0.x;
            a1 += Areg[8 * m4 + 1] * rv0.y;
            a2 += Areg[8 * m4 + 2] * rv0.z;
            a3 += Areg[8 * m4 + 3] * rv0.w;
            a4 += Areg[8 * m4 + 4] * rv1.x;
            a5 += Areg[8 * m4 + 5] * rv1.y;
            a6 += Areg[8 * m4 + 6] * rv1.z;
            a7 += Areg[8 * m4 + 7] * rv1.w;
        }
        float Ar = ((a0 + a1) + (a2 + a3)) + ((a4 + a5) + (a6 + a7));

        // p_i = r_i + beta*p_{i-1};  Ap_i = A r_i + beta*Ap_{i-1}
        float p  = rr + bcg * pold;
        float Ap = Ar + bcg * Apold;

        // exact reduction: p . Ap
        float c = p * Ap;
#pragma unroll
        for (int o = 16; o; o >>= 1) c += __shfl_xor_sync(0xffffffffu, c, o);
        if (lane == 0) redA[warp] = c;
        __syncthreads();

        float pAp = redA[0] + redA[1] + redA[2] + redA[3];
        float alpha = __fdividef(rs, pAp + 1e-12f);
        xr += alpha * p;
        rr -= alpha * Ap;
        sr[r] = rr;                   // residual for next matvec

        // exact reduction: r_new . r_new
        float s = rr * rr;
#pragma unroll
        for (int o = 16; o; o >>= 1) s += __shfl_xor_sync(0xffffffffu, s, o);
        if (lane == 0) redB[warp] = s;
        __syncthreads();

        float rsn = redB[0] + redB[1] + redB[2] + redB[3];
        bcg = __fdividef(rsn, rs + 1e-12f);
        rs = rsn;
        pold = p;
        Apold = Ap;

        if (rsn < rs_tol) break;  // converged to fp32 floor; rest are no-ops
    }

    // broadcast x via sr; reuse Areg for Hkv^T row r (o[r] = Hkv^T[r] . x)
    sr[r] = xr;
#pragma unroll
    for (int m4 = 0; m4 < 32; m4++) {
        float4 a = g_Hkv4[(mbase + m4) * 128 + r];
        Areg[4 * m4 + 0] = a.x;
        Areg[4 * m4 + 1] = a.y;
        Areg[4 * m4 + 2] = a.z;
        Areg[4 * m4 + 3] = a.w;
    }
    __syncthreads();

    {
        float a0 = 0.f, a1 = 0.f, a2 = 0.f, a3 = 0.f;
        float a4 = 0.f, a5 = 0.f, a6 = 0.f, a7 = 0.f;
#pragma unroll
        for (int m4 = 0; m4 < 16; m4++) {
            float4 xv0 = sr4[2 * m4 + 0];
            float4 xv1 = sr4[2 * m4 + 1];
            a0 += Areg[8 * m4 + 0] * xv0.x;
            a1 += Areg[8 * m4 + 1] * xv0.y;
            a2 += Areg[8 * m4 + 2] * xv0.z;
            a3 += Areg[8 * m4 + 3] * xv0.w;
            a4 += Areg[8 * m4 + 4] * xv1.x;
            a5 += Areg[8 * m4 + 5] * xv1.y;
            a6 += Areg[8 * m4 + 6] * xv1.z;
            a7 += Areg[8 * m4 + 7] * xv1.w;
        }
        float o = ((a0 + a1) + (a2 + a3)) + ((a4 + a5) + (a6 + a7));

        float s2 = o * o;
#pragma unroll
        for (int o2 = 16; o2; o2 >>= 1) s2 += __shfl_xor_sync(0xffffffffu, s2, o2);
        if (lane == 0) redB[warp] = s2;
        __syncthreads();

        float ms = (redB[0] + redB[1] + redB[2] + redB[3]) * (1.0f / 128.0f);
        g_on[(t * HH + h) * DD + r] = o * rsqrtf(ms + 1e-5f) * onw[r];
    }
}

// ---------------- launch ----------------------------------------------------
extern "C" void kernel_launch(void* const* d_in, const int* in_sizes, int n_in,
                              void* d_out, int out_size)
{
    const float* x   = (const float*)d_in[0];
    const float* Wq  = (const float*)d_in[1];
    const float* Wk  = (const float*)d_in[2];
    const float* Wv  = (const float*)d_in[3];
    const float* Wa  = (const float*)d_in[4];
    const float* ba  = (const float*)d_in[5];
    const float* Wb  = (const float*)d_in[6];
    const float* bb  = (const float*)d_in[7];
    const float* cwq = (const float*)d_in[8];
    const float* cwk = (const float*)d_in[9];
    const float* lam = (const float*)d_in[10];
    const float* onw = (const float*)d_in[11];
    const float* Wo  = (const float*)d_in[12];
    float* out = (float*)d_out;

    float *qpre, *kpre, *vbuf, *qn, *kn, *onorm;
    cudaGetSymbolAddress((void**)&qpre,  g_qpre);
    cudaGetSymbolAddress((void**)&kpre,  g_kpre);
    cudaGetSymbolAddress((void**)&vbuf,  g_v);
    cudaGetSymbolAddress((void**)&qn,    g_qn);
    cudaGetSymbolAddress((void**)&kn,    g_kn);
    cudaGetSymbolAddress((void**)&onorm, g_on);

    sgemm_qkv<<<dim3(96, 4), 256>>>(x, Wq, Wk, Wv, qpre, kpre, vbuf);          // 0
    prep_kernel<<<8192 + 256, 128>>>(x, Wa, Wb, qpre, cwq, qn, kpre, cwk, kn); // 1
    build_kernel<<<dim3(RG, HH), 256>>>(ba, bb);                               // 2
    solve_kernel<<<dim3(TT, HH), 128>>>(lam, onw);                             // 3 <- ncu
    sgemm_o<<<dim3(HIDN / 64, TT / 64), 256>>>(onorm, Wo, out);                // 4
}